// round 15
// baseline (speedup 1.0000x reference)
#include <cuda_runtime.h>
#include <cuda_fp16.h>
#include <mma.h>
#include <cstdint>

using namespace nvcuda;

#define N_NODES 512
#define SEQ     256
#define C_IN    32
#define B_SZ    8
#define C_OUT   64
#define GDEP    3
#define BETA    0.05f

#define SLICE   (N_NODES * SEQ)              // 131072 elems per (b,c) slice
#define SLOT    (B_SZ * C_IN * SLICE)        // 33554432 elems per hop slot
#define MSZ     (N_NODES * N_NODES)          // 262144 elems per 512x512 matrix

// fp16 storage: B' = (1-beta)*rownorm(A+I); M1..M3 hop matrices; X; hops.
__device__ __half g_Bp[MSZ];
__device__ __half g_M [(size_t)GDEP * MSZ];
__device__ __half g_Xh[SLOT];
__device__ __half g_hops[(size_t)GDEP * SLOT];

// ---------------------------------------------------------------------------
// cp.async helpers
// ---------------------------------------------------------------------------
__device__ __forceinline__ unsigned smem_u32(const void* p) {
    return (unsigned)__cvta_generic_to_shared(p);
}
__device__ __forceinline__ void cp16(unsigned dst, const void* src) {
    asm volatile("cp.async.cg.shared.global [%0], [%1], 16;\n" :: "r"(dst), "l"(src));
}
#define CP_COMMIT() asm volatile("cp.async.commit_group;\n")
#define CP_WAIT(n)  asm volatile("cp.async.wait_group %0;\n" :: "n"(n))

// ---------------------------------------------------------------------------
// Kernel 1: B' = (1-beta) * row-normalize(A + I); M1 = B' + beta*I. fp16.
// ---------------------------------------------------------------------------
__global__ void norm_kernel(const float* __restrict__ A) {
    int v = blockIdx.x;
    int tid = threadIdx.x;
    __shared__ float red[256];
    float s = 0.0f;
    for (int w = tid; w < N_NODES; w += 256)
        s += A[(size_t)v * N_NODES + w] + (w == v ? 1.0f : 0.0f);
    red[tid] = s;
    __syncthreads();
    for (int off = 128; off > 0; off >>= 1) {
        if (tid < off) red[tid] += red[tid + off];
        __syncthreads();
    }
    float inv = (1.0f - BETA) / red[0];
    for (int w = tid; w < N_NODES; w += 256) {
        float a = A[(size_t)v * N_NODES + w] + (w == v ? 1.0f : 0.0f);
        float bp = a * inv;
        g_Bp[(size_t)v * N_NODES + w] = __float2half_rn(bp);
        g_M[(size_t)v * N_NODES + w] = __float2half_rn(bp + (w == v ? BETA : 0.0f));
    }
}

// ---------------------------------------------------------------------------
// Kernel 1b: g_Xh = fp16(X). Each thread converts 8 elements.
// ---------------------------------------------------------------------------
__global__ void xprep_kernel(const float* __restrict__ X) {
    size_t i = ((size_t)blockIdx.x * 256 + threadIdx.x) * 8;
    float4 v0 = *(const float4*)(X + i);
    float4 v1 = *(const float4*)(X + i + 4);
    __half2 h[4];
    h[0] = __floats2half2_rn(v0.x, v0.y);
    h[1] = __floats2half2_rn(v0.z, v0.w);
    h[2] = __floats2half2_rn(v1.x, v1.y);
    h[3] = __floats2half2_rn(v1.z, v1.w);
    *(uint4*)(g_Xh + i) = *(uint4*)h;
}

// ---------------------------------------------------------------------------
// Shared GEMM geometry (hop + compose): CTA 128x128, k-chunk 64 (4 x k16),
// 4 warps (2m x 2n), warp tile 64x64, 3-stage cp.async, 128 thr, 2 CTAs/SM.
// ---------------------------------------------------------------------------
#define HK_A     9216                    // 128*72 halfs (144B rows)
#define HK_B     8704                    // 64*136 halfs (272B rows)
#define HK_STAGE (HK_A + HK_B)           // 17920 halfs = 35840 B
#define HK_SMEM  (3 * HK_STAGE * 2)      // 107520 B (compose Cs 128*132*4 fits)

// ---------------------------------------------------------------------------
// Kernel 2: compose  Mout = B' @ Min + beta*I   (512x512x512, fp16/fp32acc)
// grid 16 CTAs (4 mt x 4 nt), 128 threads.
// ---------------------------------------------------------------------------
__global__ __launch_bounds__(128, 2) void compose_kernel(const __half* __restrict__ Min,
                                                         __half* __restrict__ Mout) {
    const int mt = blockIdx.x & 3;
    const int nt = blockIdx.x >> 2;
    const int v0 = mt * 128;
    const int l0 = nt * 128;

    extern __shared__ __align__(16) char smc[];
    __half* smh = (__half*)smc;

    const int tid = threadIdx.x;
    const int wid = tid >> 5;
    const int wm = wid & 1;              // 2 warps along rows (64 each)
    const int wn = wid >> 1;             // 2 warps along cols (64 each)

    auto issue = [&](int kk, int s) {
        __half* As = smh + s * HK_STAGE;
        __half* Bs = As + HK_A;
        const int k0 = kk * 64;
#pragma unroll
        for (int i = 0; i < 8; i++) {
            int g = tid + i * 128;
            int r = g >> 3, c = g & 7;
            cp16(smem_u32(As + r * 72 + c * 8), g_Bp + (size_t)(v0 + r) * N_NODES + k0 + c * 8);
        }
#pragma unroll
        for (int i = 0; i < 8; i++) {
            int g = tid + i * 128;
            int r = g >> 4, c = g & 15;
            cp16(smem_u32(Bs + r * 136 + c * 8), Min + (size_t)(k0 + r) * N_NODES + l0 + c * 8);
        }
    };

    wmma::fragment<wmma::accumulator, 16, 16, 16, float> acc[4][4];
#pragma unroll
    for (int i = 0; i < 4; i++)
#pragma unroll
        for (int j = 0; j < 4; j++)
            wmma::fill_fragment(acc[i][j], 0.0f);

    issue(0, 0); CP_COMMIT();
    issue(1, 1); CP_COMMIT();

    for (int i = 0; i < 8; i++) {
        if (i < 7) { CP_WAIT(1); } else { CP_WAIT(0); }
        __syncthreads();
        if (i + 2 < 8) issue(i + 2, (i + 2) % 3);
        CP_COMMIT();

        const __half* As = smh + (i % 3) * HK_STAGE;
        const __half* Bs = As + HK_A;
#pragma unroll
        for (int ks = 0; ks < 4; ks++) {
            wmma::fragment<wmma::matrix_a, 16, 16, 16, __half, wmma::row_major> a[4];
            wmma::fragment<wmma::matrix_b, 16, 16, 16, __half, wmma::row_major> b[4];
#pragma unroll
            for (int mi = 0; mi < 4; mi++)
                wmma::load_matrix_sync(a[mi], As + (wm * 64 + mi * 16) * 72 + ks * 16, 72);
#pragma unroll
            for (int ni = 0; ni < 4; ni++)
                wmma::load_matrix_sync(b[ni], Bs + (ks * 16) * 136 + wn * 64 + ni * 16, 136);
#pragma unroll
            for (int mi = 0; mi < 4; mi++)
#pragma unroll
                for (int ni = 0; ni < 4; ni++)
                    wmma::mma_sync(acc[mi][ni], a[mi], b[ni], acc[mi][ni]);
        }
    }

    __syncthreads();
    float* Cs = (float*)smc;
#pragma unroll
    for (int mi = 0; mi < 4; mi++)
#pragma unroll
        for (int ni = 0; ni < 4; ni++)
            wmma::store_matrix_sync(Cs + (wm * 64 + mi * 16) * 132 + wn * 64 + ni * 16,
                                    acc[mi][ni], 132, wmma::mem_row_major);
    __syncthreads();

#pragma unroll
    for (int p = 0; p < 16; p++) {
        int id = tid + p * 128;
        int r = id >> 4, c = (id & 15) * 8;
        __half2 o[4];
#pragma unroll
        for (int q = 0; q < 4; q++) {
            float lo = Cs[r * 132 + c + q * 2];
            float hi = Cs[r * 132 + c + q * 2 + 1];
            if (v0 + r == l0 + c + q * 2)     lo += BETA;
            if (v0 + r == l0 + c + q * 2 + 1) hi += BETA;
            o[q] = __floats2half2_rn(lo, hi);
        }
        *(uint4*)(Mout + (size_t)(v0 + r) * N_NODES + l0 + c) = *(uint4*)o;
    }
}

// ---------------------------------------------------------------------------
// Kernel 3: fused hop GEMM. Hk = M[z] @ X per (b,c) slice, all 3 hops in one
// launch. grid (8, 256, 3), 128 threads, 2 CTAs/SM.
// Epilogue: fp32 acc -> fp16 acc fragment (same-shape elementwise map) ->
// store_matrix_sync DIRECTLY to global (no smem round-trip, no barriers).
// ---------------------------------------------------------------------------
__global__ __launch_bounds__(128, 2) void hop_kernel() {
    const int bc = blockIdx.y;
    const int mt = blockIdx.x & 3;       // 4 row tiles of 128
    const int nt = blockIdx.x >> 2;      // 2 col tiles of 128
    const int hop = blockIdx.z;
    const size_t sbase = (size_t)bc * SLICE;
    const int v0 = mt * 128;
    const int l0 = nt * 128;

    const __half* __restrict__ Amat = g_M + (size_t)hop * MSZ;
    const __half* __restrict__ src  = g_Xh + sbase;
    __half* __restrict__ dst = g_hops + (size_t)hop * SLOT + sbase;

    extern __shared__ __align__(16) char smc[];
    __half* smh = (__half*)smc;

    const int tid = threadIdx.x;
    const int wid = tid >> 5;
    const int wm = wid & 1;              // 2 warps along rows (64 each)
    const int wn = wid >> 1;             // 2 warps along cols (64 each)

    auto issue = [&](int kk, int s) {
        __half* As = smh + s * HK_STAGE;
        __half* Bs = As + HK_A;
        const int k0 = kk * 64;
#pragma unroll
        for (int i = 0; i < 8; i++) {    // M tile 128x64 halfs
            int g = tid + i * 128;
            int r = g >> 3, c = g & 7;
            cp16(smem_u32(As + r * 72 + c * 8), Amat + (size_t)(v0 + r) * N_NODES + k0 + c * 8);
        }
#pragma unroll
        for (int i = 0; i < 8; i++) {    // X tile 64x128 halfs
            int g = tid + i * 128;
            int r = g >> 4, c = g & 15;
            cp16(smem_u32(Bs + r * 136 + c * 8), src + (size_t)(k0 + r) * SEQ + l0 + c * 8);
        }
    };

    wmma::fragment<wmma::accumulator, 16, 16, 16, float> acc[4][4];
#pragma unroll
    for (int i = 0; i < 4; i++)
#pragma unroll
        for (int j = 0; j < 4; j++)
            wmma::fill_fragment(acc[i][j], 0.0f);

    issue(0, 0); CP_COMMIT();
    issue(1, 1); CP_COMMIT();

    for (int i = 0; i < 8; i++) {
        if (i < 7) { CP_WAIT(1); } else { CP_WAIT(0); }
        __syncthreads();
        if (i + 2 < 8) issue(i + 2, (i + 2) % 3);
        CP_COMMIT();

        const __half* As = smh + (i % 3) * HK_STAGE;
        const __half* Bs = As + HK_A;
#pragma unroll
        for (int ks = 0; ks < 4; ks++) {
            wmma::fragment<wmma::matrix_a, 16, 16, 16, __half, wmma::row_major> a[4];
            wmma::fragment<wmma::matrix_b, 16, 16, 16, __half, wmma::row_major> b[4];
#pragma unroll
            for (int mi = 0; mi < 4; mi++)
                wmma::load_matrix_sync(a[mi], As + (wm * 64 + mi * 16) * 72 + ks * 16, 72);
#pragma unroll
            for (int ni = 0; ni < 4; ni++)
                wmma::load_matrix_sync(b[ni], Bs + (ks * 16) * 136 + wn * 64 + ni * 16, 136);
#pragma unroll
            for (int mi = 0; mi < 4; mi++)
#pragma unroll
                for (int ni = 0; ni < 4; ni++)
                    wmma::mma_sync(acc[mi][ni], a[mi], b[ni], acc[mi][ni]);
        }
    }

    // Epilogue: direct fp16 store to global (beta*X folded into M).
#pragma unroll
    for (int mi = 0; mi < 4; mi++) {
#pragma unroll
        for (int ni = 0; ni < 4; ni++) {
            wmma::fragment<wmma::accumulator, 16, 16, 16, __half> hf;
#pragma unroll
            for (int e = 0; e < hf.num_elements; e++)
                hf.x[e] = __float2half_rn(acc[mi][ni].x[e]);
            wmma::store_matrix_sync(dst + (size_t)(v0 + wm * 64 + mi * 16) * SEQ
                                        + l0 + wn * 64 + ni * 16,
                                    hf, SEQ, wmma::mem_row_major);
        }
    }
}

// ---------------------------------------------------------------------------
// Kernel 4: 1x1 conv, fp16 HMMA. out[64,131072] = W[64,128] @ Hcat + bias.
// CTA 64 x 128, K=128 as 2 chunks of 64, both prefetched (2-stage).
// 128 threads, 4 warps (2m x 2n), warp tile 32x64. grid (1024, 8), 3 CTAs/SM.
// ---------------------------------------------------------------------------
#define CV_WS    8704                    // 64*136 halfs = 17408 B (W resident)
#define CV_BS    8704                    // 64*136 halfs = 17408 B per stage
#define CV_SMEM  ((CV_WS + 2 * CV_BS) * 2)   // 52224 B (Cs 64*132*4=33792 fits)

__global__ __launch_bounds__(128, 3) void conv_kernel(const float* __restrict__ W,
                                                      const float* __restrict__ bias,
                                                      float* __restrict__ out) {
    const int b = blockIdx.y;
    const int col0 = blockIdx.x * 128;

    extern __shared__ __align__(16) char smc[];
    __half* Ws = (__half*)smc;

    const int tid = threadIdx.x;
    const int wid = tid >> 5;
    const int wm = wid & 1;              // 2 warps x 32 rows
    const int wn = wid >> 1;             // 2 warps x 64 cols

    auto issue = [&](int kk) {
        __half* Bs = Ws + CV_WS + kk * CV_BS;
        const int k0 = kk * 64;
#pragma unroll
        for (int i = 0; i < 8; i++) {    // 64 k-rows x 128 cols = 1024 granules
            int g = tid + i * 128;
            int r = g >> 4, c = g & 15;
            int ch = k0 + r;
            const __half* rp = (ch < C_IN)
                ? (g_Xh + ((size_t)b * C_IN + ch) * SLICE)
                : (g_hops + (size_t)((ch >> 5) - 1) * SLOT + ((size_t)b * C_IN + (ch & 31)) * SLICE);
            cp16(smem_u32(Bs + r * 136 + c * 8), rp + col0 + c * 8);
        }
        CP_COMMIT();
    };

    issue(0);
    issue(1);

    // Load W (64x128) -> fp16 smem (overlaps the cp.async)
#pragma unroll
    for (int p = 0; p < 8; p++) {
        int id = tid + p * 128;
        int r = id >> 4, c = (id & 15) * 8;
        float4 v0 = *(const float4*)(W + r * 128 + c);
        float4 v1 = *(const float4*)(W + r * 128 + c + 4);
        __half2 h[4];
        h[0] = __floats2half2_rn(v0.x, v0.y);
        h[1] = __floats2half2_rn(v0.z, v0.w);
        h[2] = __floats2half2_rn(v1.x, v1.y);
        h[3] = __floats2half2_rn(v1.z, v1.w);
        *(uint4*)(Ws + r * 136 + c) = *(uint4*)h;
    }

    wmma::fragment<wmma::accumulator, 16, 16, 16, float> acc[2][4];
#pragma unroll
    for (int i = 0; i < 2; i++)
#pragma unroll
        for (int j = 0; j < 4; j++)
            wmma::fill_fragment(acc[i][j], 0.0f);

#pragma unroll
    for (int i = 0; i < 2; i++) {
        if (i == 0) { CP_WAIT(1); } else { CP_WAIT(0); }
        __syncthreads();

        const __half* Bs = Ws + CV_WS + i * CV_BS;
        const int k0 = i * 64;
#pragma unroll
        for (int ks = 0; ks < 4; ks++) {
            wmma::fragment<wmma::matrix_a, 16, 16, 16, __half, wmma::row_major> a[2];
            wmma::fragment<wmma::matrix_b, 16, 16, 16, __half, wmma::row_major> bb[4];
#pragma unroll
            for (int mi = 0; mi < 2; mi++)
                wmma::load_matrix_sync(a[mi], Ws + (wm * 32 + mi * 16) * 136 + k0 + ks * 16, 136);
#pragma unroll
            for (int ni = 0; ni < 4; ni++)
                wmma::load_matrix_sync(bb[ni], Bs + (ks * 16) * 136 + wn * 64 + ni * 16, 136);
#pragma unroll
            for (int mi = 0; mi < 2; mi++)
#pragma unroll
                for (int ni = 0; ni < 4; ni++)
                    wmma::mma_sync(acc[mi][ni], a[mi], bb[ni], acc[mi][ni]);
        }
    }

    __syncthreads();
    float* Cs = (float*)smc;  // [64][132] = 33792 B, overlays Ws+Bs (done)
#pragma unroll
    for (int mi = 0; mi < 2; mi++)
#pragma unroll
        for (int ni = 0; ni < 4; ni++)
            wmma::store_matrix_sync(Cs + (wm * 32 + mi * 16) * 132 + wn * 64 + ni * 16,
                                    acc[mi][ni], 132, wmma::mem_row_major);
    __syncthreads();

    const size_t obase = (size_t)b * C_OUT * SLICE;
#pragma unroll
    for (int p = 0; p < 16; p++) {
        int id = tid + p * 128;
        int r = id >> 5, c = (id & 31) * 4;
        float bv = __ldg(bias + r);
        float4 cv = *(const float4*)(Cs + r * 132 + c);
        cv.x += bv; cv.y += bv; cv.z += bv; cv.w += bv;
        *(float4*)(out + obase + (size_t)r * SLICE + col0 + c) = cv;
    }
}

// ---------------------------------------------------------------------------
extern "C" void kernel_launch(void* const* d_in, const int* in_sizes, int n_in,
                              void* d_out, int out_size) {
    const float* X    = (const float*)d_in[0];   // [8,32,512,256]
    const float* A    = (const float*)d_in[1];   // [512,512]
    const float* W    = (const float*)d_in[2];   // [64,128]
    const float* bias = (const float*)d_in[3];   // [64]
    float* out = (float*)d_out;                  // [8,64,512,256]

    cudaFuncSetAttribute(hop_kernel,     cudaFuncAttributeMaxDynamicSharedMemorySize, HK_SMEM);
    cudaFuncSetAttribute(compose_kernel, cudaFuncAttributeMaxDynamicSharedMemorySize, HK_SMEM);
    cudaFuncSetAttribute(conv_kernel,    cudaFuncAttributeMaxDynamicSharedMemorySize, CV_SMEM);
    cudaFuncSetAttribute(hop_kernel,     cudaFuncAttributePreferredSharedMemoryCarveout, 100);
    cudaFuncSetAttribute(compose_kernel, cudaFuncAttributePreferredSharedMemoryCarveout, 100);
    cudaFuncSetAttribute(conv_kernel,    cudaFuncAttributePreferredSharedMemoryCarveout, 100);

    norm_kernel<<<N_NODES, 256>>>(A);          // writes B' and M1
    xprep_kernel<<<SLOT / (256 * 8), 256>>>(X);

    __half* M;
    cudaGetSymbolAddress((void**)&M, g_M);
    compose_kernel<<<16, 128, HK_SMEM>>>(M,           M + 1 * MSZ);  // M2 = B'M1 + bI
    compose_kernel<<<16, 128, HK_SMEM>>>(M + 1 * MSZ, M + 2 * MSZ);  // M3 = B'M2 + bI

    dim3 hg(8, B_SZ * C_IN, GDEP);
    hop_kernel<<<hg, 128, HK_SMEM>>>();        // H1, H2, H3 in one launch

    dim3 cg(SLICE / 128, B_SZ);
    conv_kernel<<<cg, 128, CV_SMEM>>>(W, bias, out);
}

// round 16
// speedup vs baseline: 1.0340x; 1.0340x over previous
#include <cuda_runtime.h>
#include <cuda_fp16.h>
#include <mma.h>
#include <cstdint>

using namespace nvcuda;

#define N_NODES 512
#define SEQ     256
#define C_IN    32
#define B_SZ    8
#define C_OUT   64
#define GDEP    3
#define BETA    0.05f

#define SLICE   (N_NODES * SEQ)              // 131072 elems per (b,c) slice
#define SLOT    (B_SZ * C_IN * SLICE)        // 33554432 elems per hop slot
#define MSZ     (N_NODES * N_NODES)          // 262144 elems per 512x512 matrix

// fp16 storage: B' = (1-beta)*rownorm(A+I); M1..M3 hop matrices; X; hops.
__device__ __half g_Bp[MSZ];
__device__ __half g_M [(size_t)GDEP * MSZ];
__device__ __half g_Xh[SLOT];
__device__ __half g_hops[(size_t)GDEP * SLOT];

// ---------------------------------------------------------------------------
// cp.async helpers
// ---------------------------------------------------------------------------
__device__ __forceinline__ unsigned smem_u32(const void* p) {
    return (unsigned)__cvta_generic_to_shared(p);
}
__device__ __forceinline__ void cp16(unsigned dst, const void* src) {
    asm volatile("cp.async.cg.shared.global [%0], [%1], 16;\n" :: "r"(dst), "l"(src));
}
#define CP_COMMIT() asm volatile("cp.async.commit_group;\n")
#define CP_WAIT(n)  asm volatile("cp.async.wait_group %0;\n" :: "n"(n))

// ---------------------------------------------------------------------------
// Kernel 1: B' = (1-beta) * row-normalize(A + I); M1 = B' + beta*I. fp16.
// ---------------------------------------------------------------------------
__global__ void norm_kernel(const float* __restrict__ A) {
    int v = blockIdx.x;
    int tid = threadIdx.x;
    __shared__ float red[256];
    float s = 0.0f;
    for (int w = tid; w < N_NODES; w += 256)
        s += A[(size_t)v * N_NODES + w] + (w == v ? 1.0f : 0.0f);
    red[tid] = s;
    __syncthreads();
    for (int off = 128; off > 0; off >>= 1) {
        if (tid < off) red[tid] += red[tid + off];
        __syncthreads();
    }
    float inv = (1.0f - BETA) / red[0];
    for (int w = tid; w < N_NODES; w += 256) {
        float a = A[(size_t)v * N_NODES + w] + (w == v ? 1.0f : 0.0f);
        float bp = a * inv;
        g_Bp[(size_t)v * N_NODES + w] = __float2half_rn(bp);
        g_M[(size_t)v * N_NODES + w] = __float2half_rn(bp + (w == v ? BETA : 0.0f));
    }
}

// ---------------------------------------------------------------------------
// Kernel 1b: g_Xh = fp16(X). Each thread converts 16 elements (MLP=4).
// ---------------------------------------------------------------------------
__global__ void xprep_kernel(const float* __restrict__ X) {
    size_t i = ((size_t)blockIdx.x * 256 + threadIdx.x) * 16;
    float4 v0 = *(const float4*)(X + i);
    float4 v1 = *(const float4*)(X + i + 4);
    float4 v2 = *(const float4*)(X + i + 8);
    float4 v3 = *(const float4*)(X + i + 12);
    __half2 h[8];
    h[0] = __floats2half2_rn(v0.x, v0.y);
    h[1] = __floats2half2_rn(v0.z, v0.w);
    h[2] = __floats2half2_rn(v1.x, v1.y);
    h[3] = __floats2half2_rn(v1.z, v1.w);
    h[4] = __floats2half2_rn(v2.x, v2.y);
    h[5] = __floats2half2_rn(v2.z, v2.w);
    h[6] = __floats2half2_rn(v3.x, v3.y);
    h[7] = __floats2half2_rn(v3.z, v3.w);
    *(uint4*)(g_Xh + i)     = *(uint4*)h;
    *(uint4*)(g_Xh + i + 8) = *(uint4*)(h + 4);
}

// ---------------------------------------------------------------------------
// Shared GEMM geometry (hop + compose): CTA 128x128, k-chunk 64 (4 x k16),
// 4 warps (2m x 2n), warp tile 64x64, 3-stage cp.async, 128 thr, 2 CTAs/SM.
// ---------------------------------------------------------------------------
#define HK_A     9216                    // 128*72 halfs (144B rows)
#define HK_B     8704                    // 64*136 halfs (272B rows)
#define HK_STAGE (HK_A + HK_B)           // 17920 halfs = 35840 B
#define HK_SMEM  (3 * HK_STAGE * 2)      // 107520 B (compose Cs 128*132*4 fits)

// ---------------------------------------------------------------------------
// Kernel 2: compose  Mout = B' @ Min + beta*I   (512x512x512, fp16/fp32acc)
// grid 16 CTAs (4 mt x 4 nt), 128 threads.
// ---------------------------------------------------------------------------
__global__ __launch_bounds__(128, 2) void compose_kernel(const __half* __restrict__ Min,
                                                         __half* __restrict__ Mout) {
    const int mt = blockIdx.x & 3;
    const int nt = blockIdx.x >> 2;
    const int v0 = mt * 128;
    const int l0 = nt * 128;

    extern __shared__ __align__(16) char smc[];
    __half* smh = (__half*)smc;

    const int tid = threadIdx.x;
    const int wid = tid >> 5;
    const int wm = wid & 1;              // 2 warps along rows (64 each)
    const int wn = wid >> 1;             // 2 warps along cols (64 each)

    auto issue = [&](int kk, int s) {
        __half* As = smh + s * HK_STAGE;
        __half* Bs = As + HK_A;
        const int k0 = kk * 64;
#pragma unroll
        for (int i = 0; i < 8; i++) {
            int g = tid + i * 128;
            int r = g >> 3, c = g & 7;
            cp16(smem_u32(As + r * 72 + c * 8), g_Bp + (size_t)(v0 + r) * N_NODES + k0 + c * 8);
        }
#pragma unroll
        for (int i = 0; i < 8; i++) {
            int g = tid + i * 128;
            int r = g >> 4, c = g & 15;
            cp16(smem_u32(Bs + r * 136 + c * 8), Min + (size_t)(k0 + r) * N_NODES + l0 + c * 8);
        }
    };

    wmma::fragment<wmma::accumulator, 16, 16, 16, float> acc[4][4];
#pragma unroll
    for (int i = 0; i < 4; i++)
#pragma unroll
        for (int j = 0; j < 4; j++)
            wmma::fill_fragment(acc[i][j], 0.0f);

    issue(0, 0); CP_COMMIT();
    issue(1, 1); CP_COMMIT();

    for (int i = 0; i < 8; i++) {
        if (i < 7) { CP_WAIT(1); } else { CP_WAIT(0); }
        __syncthreads();
        if (i + 2 < 8) issue(i + 2, (i + 2) % 3);
        CP_COMMIT();

        const __half* As = smh + (i % 3) * HK_STAGE;
        const __half* Bs = As + HK_A;
#pragma unroll
        for (int ks = 0; ks < 4; ks++) {
            wmma::fragment<wmma::matrix_a, 16, 16, 16, __half, wmma::row_major> a[4];
            wmma::fragment<wmma::matrix_b, 16, 16, 16, __half, wmma::row_major> b[4];
#pragma unroll
            for (int mi = 0; mi < 4; mi++)
                wmma::load_matrix_sync(a[mi], As + (wm * 64 + mi * 16) * 72 + ks * 16, 72);
#pragma unroll
            for (int ni = 0; ni < 4; ni++)
                wmma::load_matrix_sync(b[ni], Bs + (ks * 16) * 136 + wn * 64 + ni * 16, 136);
#pragma unroll
            for (int mi = 0; mi < 4; mi++)
#pragma unroll
                for (int ni = 0; ni < 4; ni++)
                    wmma::mma_sync(acc[mi][ni], a[mi], b[ni], acc[mi][ni]);
        }
    }

    __syncthreads();
    float* Cs = (float*)smc;
#pragma unroll
    for (int mi = 0; mi < 4; mi++)
#pragma unroll
        for (int ni = 0; ni < 4; ni++)
            wmma::store_matrix_sync(Cs + (wm * 64 + mi * 16) * 132 + wn * 64 + ni * 16,
                                    acc[mi][ni], 132, wmma::mem_row_major);
    __syncthreads();

#pragma unroll
    for (int p = 0; p < 16; p++) {
        int id = tid + p * 128;
        int r = id >> 4, c = (id & 15) * 8;
        __half2 o[4];
#pragma unroll
        for (int q = 0; q < 4; q++) {
            float lo = Cs[r * 132 + c + q * 2];
            float hi = Cs[r * 132 + c + q * 2 + 1];
            if (v0 + r == l0 + c + q * 2)     lo += BETA;
            if (v0 + r == l0 + c + q * 2 + 1) hi += BETA;
            o[q] = __floats2half2_rn(lo, hi);
        }
        *(uint4*)(Mout + (size_t)(v0 + r) * N_NODES + l0 + c) = *(uint4*)o;
    }
}

// ---------------------------------------------------------------------------
// Kernel 3: fused hop GEMM. Hk = M[z] @ X per (b,c) slice, all 3 hops in one
// launch. grid (8, 256, 3), 128 threads, 2 CTAs/SM.
// Epilogue: fp32 acc -> fp16 acc frag (validated in R14) -> fp16 smem stage
// (half the crossbar bytes of fp32 staging) -> coalesced uint4 STG.
// ---------------------------------------------------------------------------
__global__ __launch_bounds__(128, 2) void hop_kernel() {
    const int bc = blockIdx.y;
    const int mt = blockIdx.x & 3;       // 4 row tiles of 128
    const int nt = blockIdx.x >> 2;      // 2 col tiles of 128
    const int hop = blockIdx.z;
    const size_t sbase = (size_t)bc * SLICE;
    const int v0 = mt * 128;
    const int l0 = nt * 128;

    const __half* __restrict__ Amat = g_M + (size_t)hop * MSZ;
    const __half* __restrict__ src  = g_Xh + sbase;
    __half* __restrict__ dst = g_hops + (size_t)hop * SLOT + sbase;

    extern __shared__ __align__(16) char smc[];
    __half* smh = (__half*)smc;

    const int tid = threadIdx.x;
    const int wid = tid >> 5;
    const int wm = wid & 1;              // 2 warps along rows (64 each)
    const int wn = wid >> 1;             // 2 warps along cols (64 each)

    auto issue = [&](int kk, int s) {
        __half* As = smh + s * HK_STAGE;
        __half* Bs = As + HK_A;
        const int k0 = kk * 64;
#pragma unroll
        for (int i = 0; i < 8; i++) {    // M tile 128x64 halfs
            int g = tid + i * 128;
            int r = g >> 3, c = g & 7;
            cp16(smem_u32(As + r * 72 + c * 8), Amat + (size_t)(v0 + r) * N_NODES + k0 + c * 8);
        }
#pragma unroll
        for (int i = 0; i < 8; i++) {    // X tile 64x128 halfs
            int g = tid + i * 128;
            int r = g >> 4, c = g & 15;
            cp16(smem_u32(Bs + r * 136 + c * 8), src + (size_t)(k0 + r) * SEQ + l0 + c * 8);
        }
    };

    wmma::fragment<wmma::accumulator, 16, 16, 16, float> acc[4][4];
#pragma unroll
    for (int i = 0; i < 4; i++)
#pragma unroll
        for (int j = 0; j < 4; j++)
            wmma::fill_fragment(acc[i][j], 0.0f);

    issue(0, 0); CP_COMMIT();
    issue(1, 1); CP_COMMIT();

    for (int i = 0; i < 8; i++) {
        if (i < 7) { CP_WAIT(1); } else { CP_WAIT(0); }
        __syncthreads();
        if (i + 2 < 8) issue(i + 2, (i + 2) % 3);
        CP_COMMIT();

        const __half* As = smh + (i % 3) * HK_STAGE;
        const __half* Bs = As + HK_A;
#pragma unroll
        for (int ks = 0; ks < 4; ks++) {
            wmma::fragment<wmma::matrix_a, 16, 16, 16, __half, wmma::row_major> a[4];
            wmma::fragment<wmma::matrix_b, 16, 16, 16, __half, wmma::row_major> b[4];
#pragma unroll
            for (int mi = 0; mi < 4; mi++)
                wmma::load_matrix_sync(a[mi], As + (wm * 64 + mi * 16) * 72 + ks * 16, 72);
#pragma unroll
            for (int ni = 0; ni < 4; ni++)
                wmma::load_matrix_sync(b[ni], Bs + (ks * 16) * 136 + wn * 64 + ni * 16, 136);
#pragma unroll
            for (int mi = 0; mi < 4; mi++)
#pragma unroll
                for (int ni = 0; ni < 4; ni++)
                    wmma::mma_sync(acc[mi][ni], a[mi], b[ni], acc[mi][ni]);
        }
    }

    __syncthreads();
    // Epilogue: fp16 staging (beta*X folded into M via beta*I term).
    __half* Cs = (__half*)smc;           // [128][136] halfs = 34816 B
#pragma unroll
    for (int mi = 0; mi < 4; mi++) {
#pragma unroll
        for (int ni = 0; ni < 4; ni++) {
            wmma::fragment<wmma::accumulator, 16, 16, 16, __half> hf;
#pragma unroll
            for (int e = 0; e < hf.num_elements; e++)
                hf.x[e] = __float2half_rn(acc[mi][ni].x[e]);
            wmma::store_matrix_sync(Cs + (wm * 64 + mi * 16) * 136 + wn * 64 + ni * 16,
                                    hf, 136, wmma::mem_row_major);
        }
    }
    __syncthreads();

#pragma unroll
    for (int p = 0; p < 16; p++) {       // 128x128 halfs, 8-elem groups
        int id = tid + p * 128;
        int r = id >> 4, c = (id & 15) * 8;
        *(uint4*)(dst + (size_t)(v0 + r) * SEQ + l0 + c) = *(const uint4*)(Cs + r * 136 + c);
    }
}

// ---------------------------------------------------------------------------
// Kernel 4: 1x1 conv, fp16 HMMA. out[64,131072] = W[64,128] @ Hcat + bias.
// CTA 64 x 128, K=128 as 2 chunks of 64, both prefetched (2-stage).
// 128 threads, 4 warps (2m x 2n), warp tile 32x64. grid (1024, 8), 3 CTAs/SM.
// ---------------------------------------------------------------------------
#define CV_WS    8704                    // 64*136 halfs = 17408 B (W resident)
#define CV_BS    8704                    // 64*136 halfs = 17408 B per stage
#define CV_SMEM  ((CV_WS + 2 * CV_BS) * 2)   // 52224 B (Cs 64*132*4=33792 fits)

__global__ __launch_bounds__(128, 3) void conv_kernel(const float* __restrict__ W,
                                                      const float* __restrict__ bias,
                                                      float* __restrict__ out) {
    const int b = blockIdx.y;
    const int col0 = blockIdx.x * 128;

    extern __shared__ __align__(16) char smc[];
    __half* Ws = (__half*)smc;

    const int tid = threadIdx.x;
    const int wid = tid >> 5;
    const int wm = wid & 1;              // 2 warps x 32 rows
    const int wn = wid >> 1;             // 2 warps x 64 cols

    auto issue = [&](int kk) {
        __half* Bs = Ws + CV_WS + kk * CV_BS;
        const int k0 = kk * 64;
#pragma unroll
        for (int i = 0; i < 8; i++) {    // 64 k-rows x 128 cols = 1024 granules
            int g = tid + i * 128;
            int r = g >> 4, c = g & 15;
            int ch = k0 + r;
            const __half* rp = (ch < C_IN)
                ? (g_Xh + ((size_t)b * C_IN + ch) * SLICE)
                : (g_hops + (size_t)((ch >> 5) - 1) * SLOT + ((size_t)b * C_IN + (ch & 31)) * SLICE);
            cp16(smem_u32(Bs + r * 136 + c * 8), rp + col0 + c * 8);
        }
        CP_COMMIT();
    };

    issue(0);
    issue(1);

    // Load W (64x128) -> fp16 smem (overlaps the cp.async)
#pragma unroll
    for (int p = 0; p < 8; p++) {
        int id = tid + p * 128;
        int r = id >> 4, c = (id & 15) * 8;
        float4 v0 = *(const float4*)(W + r * 128 + c);
        float4 v1 = *(const float4*)(W + r * 128 + c + 4);
        __half2 h[4];
        h[0] = __floats2half2_rn(v0.x, v0.y);
        h[1] = __floats2half2_rn(v0.z, v0.w);
        h[2] = __floats2half2_rn(v1.x, v1.y);
        h[3] = __floats2half2_rn(v1.z, v1.w);
        *(uint4*)(Ws + r * 136 + c) = *(uint4*)h;
    }

    wmma::fragment<wmma::accumulator, 16, 16, 16, float> acc[2][4];
#pragma unroll
    for (int i = 0; i < 2; i++)
#pragma unroll
        for (int j = 0; j < 4; j++)
            wmma::fill_fragment(acc[i][j], 0.0f);

#pragma unroll
    for (int i = 0; i < 2; i++) {
        if (i == 0) { CP_WAIT(1); } else { CP_WAIT(0); }
        __syncthreads();

        const __half* Bs = Ws + CV_WS + i * CV_BS;
        const int k0 = i * 64;
#pragma unroll
        for (int ks = 0; ks < 4; ks++) {
            wmma::fragment<wmma::matrix_a, 16, 16, 16, __half, wmma::row_major> a[2];
            wmma::fragment<wmma::matrix_b, 16, 16, 16, __half, wmma::row_major> bb[4];
#pragma unroll
            for (int mi = 0; mi < 2; mi++)
                wmma::load_matrix_sync(a[mi], Ws + (wm * 32 + mi * 16) * 136 + k0 + ks * 16, 136);
#pragma unroll
            for (int ni = 0; ni < 4; ni++)
                wmma::load_matrix_sync(bb[ni], Bs + (ks * 16) * 136 + wn * 64 + ni * 16, 136);
#pragma unroll
            for (int mi = 0; mi < 2; mi++)
#pragma unroll
                for (int ni = 0; ni < 4; ni++)
                    wmma::mma_sync(acc[mi][ni], a[mi], bb[ni], acc[mi][ni]);
        }
    }

    __syncthreads();
    float* Cs = (float*)smc;  // [64][132] = 33792 B, overlays Ws+Bs (done)
#pragma unroll
    for (int mi = 0; mi < 2; mi++)
#pragma unroll
        for (int ni = 0; ni < 4; ni++)
            wmma::store_matrix_sync(Cs + (wm * 32 + mi * 16) * 132 + wn * 64 + ni * 16,
                                    acc[mi][ni], 132, wmma::mem_row_major);
    __syncthreads();

    const size_t obase = (size_t)b * C_OUT * SLICE;
#pragma unroll
    for (int p = 0; p < 16; p++) {
        int id = tid + p * 128;
        int r = id >> 5, c = (id & 31) * 4;
        float bv = __ldg(bias + r);
        float4 cv = *(const float4*)(Cs + r * 132 + c);
        cv.x += bv; cv.y += bv; cv.z += bv; cv.w += bv;
        *(float4*)(out + obase + (size_t)r * SLICE + col0 + c) = cv;
    }
}

// ---------------------------------------------------------------------------
extern "C" void kernel_launch(void* const* d_in, const int* in_sizes, int n_in,
                              void* d_out, int out_size) {
    const float* X    = (const float*)d_in[0];   // [8,32,512,256]
    const float* A    = (const float*)d_in[1];   // [512,512]
    const float* W    = (const float*)d_in[2];   // [64,128]
    const float* bias = (const float*)d_in[3];   // [64]
    float* out = (float*)d_out;                  // [8,64,512,256]

    cudaFuncSetAttribute(hop_kernel,     cudaFuncAttributeMaxDynamicSharedMemorySize, HK_SMEM);
    cudaFuncSetAttribute(compose_kernel, cudaFuncAttributeMaxDynamicSharedMemorySize, HK_SMEM);
    cudaFuncSetAttribute(conv_kernel,    cudaFuncAttributeMaxDynamicSharedMemorySize, CV_SMEM);
    cudaFuncSetAttribute(hop_kernel,     cudaFuncAttributePreferredSharedMemoryCarveout, 100);
    cudaFuncSetAttribute(compose_kernel, cudaFuncAttributePreferredSharedMemoryCarveout, 100);
    cudaFuncSetAttribute(conv_kernel,    cudaFuncAttributePreferredSharedMemoryCarveout, 100);

    norm_kernel<<<N_NODES, 256>>>(A);          // writes B' and M1
    xprep_kernel<<<SLOT / (256 * 16), 256>>>(X);

    __half* M;
    cudaGetSymbolAddress((void**)&M, g_M);
    compose_kernel<<<16, 128, HK_SMEM>>>(M,           M + 1 * MSZ);  // M2 = B'M1 + bI
    compose_kernel<<<16, 128, HK_SMEM>>>(M + 1 * MSZ, M + 2 * MSZ);  // M3 = B'M2 + bI

    dim3 hg(8, B_SZ * C_IN, GDEP);
    hop_kernel<<<hg, 128, HK_SMEM>>>();        // H1, H2, H3 in one launch

    dim3 cg(SLICE / 128, B_SZ);
    conv_kernel<<<cg, 128, CV_SMEM>>>(W, bias, out);
}